// round 9
// baseline (speedup 1.0000x reference)
#include <cuda_runtime.h>
#include <cstdint>

#define NP 256
#define NG 1024
#define F  128
#define EPSV 1e-5f

#define TP 16
#define TG 64
#define KC 64          // features per split (F / gridDim.z)
#define THREADS 128

// ---------------- f32x2 helpers ----------------
__device__ __forceinline__ unsigned long long fma2(unsigned long long a,
                                                   unsigned long long b,
                                                   unsigned long long c) {
    unsigned long long d;
    asm("fma.rn.f32x2 %0, %1, %2, %3;" : "=l"(d) : "l"(a), "l"(b), "l"(c));
    return d;
}
__device__ __forceinline__ unsigned long long dup2(float x) {
    unsigned long long d;
    asm("mov.b64 %0, {%1, %1};" : "=l"(d) : "f"(x));
    return d;
}
__device__ __forceinline__ float2 unpack2(unsigned long long v) {
    float2 r;
    asm("mov.b64 {%0, %1}, %2;" : "=f"(r.x), "=f"(r.y) : "l"(v));
    return r;
}

// ---------------- split-K fused kernel ----------------
// Each (bx,by,kz) block accumulates the partial of
//   out[p,g,c] = A[p,c] + B[g,c] + K[c] - 2 * sum_f (p_f w'_cf) g_f
// over f in [kz*KC, kz*KC+KC), via atomicAdd into zeroed d_out.
__global__ void __launch_bounds__(THREADS, 4) cls_kernel(
    const float* __restrict__ probe, const float* __restrict__ gal,
    const float* __restrict__ bnw, const float* __restrict__ bnb,
    const float* __restrict__ bnm, const float* __restrict__ bnv,
    const float* __restrict__ W, const float* __restrict__ bias,
    float* __restrict__ out)
{
    // Rows = 272 B (17*16); sizes are 16-multiples; all 16B accesses aligned.
    __shared__ __align__(16) unsigned long long sPd[KC + 1][2 * TP + 2]; // [f][2p+c] dup'd
    __shared__ __align__(16) float sG[KC + 1][TG + 4];                   // [f][g] raw
    __shared__ float2 sA[TP];
    __shared__ float2 sB[TG];

    const int tid  = threadIdx.x;
    const int lane = tid & 31;
    const int warp = tid >> 5;      // 0..3
    const int bp = blockIdx.y * TP;
    const int bg = blockIdx.x * TG;
    const int fbase = blockIdx.z * KC;

    // -------- folded weights for this split (f = fbase + lane + 32i, i<2) --------
    float w0r[2], w1r[2];
    float kc0 = 0.f, kc1 = 0.f;
    #pragma unroll
    for (int i = 0; i < 2; i++) {
        const int f = fbase + lane + 32 * i;
        const float inv = bnw[f] * rsqrtf(bnv[f] + EPSV);
        const float Wf0 = W[f], Wf1 = W[F + f];
        w0r[i] = Wf0 * inv;
        w1r[i] = Wf1 * inv;
        const float off = bnb[f] - bnm[f] * inv;
        kc0 = fmaf(Wf0, off, kc0);
        kc1 = fmaf(Wf1, off, kc1);
    }
    #pragma unroll
    for (int o = 16; o > 0; o >>= 1) {
        kc0 += __shfl_xor_sync(0xffffffffu, kc0, o);
        kc1 += __shfl_xor_sync(0xffffffffu, kc1, o);
    }
    if (blockIdx.z == 0) {          // bias belongs to exactly one split
        kc0 += bias[0];
        kc1 += bias[1];
    }

    // -------- load + scale probes (fused A partials), dup'd into smem --------
    float pa0[4], pa1[4];
    #pragma unroll
    for (int k = 0; k < 4; k++) { pa0[k] = 0.f; pa1[k] = 0.f; }
    #pragma unroll
    for (int k = 0; k < 4; k++) {
        const int p = warp + 4 * k;               // 16 probes
        const float* src = probe + (size_t)(bp + p) * F + fbase;
        const float x0 = src[lane];
        const float x1 = src[lane + 32];
        const float s00 = x0 * w0r[0], s01 = x0 * w1r[0];
        const float s10 = x1 * w0r[1], s11 = x1 * w1r[1];
        *(ulonglong2*)&sPd[lane][2 * p]      = make_ulonglong2(dup2(s00), dup2(s01));
        *(ulonglong2*)&sPd[lane + 32][2 * p] = make_ulonglong2(dup2(s10), dup2(s11));
        pa0[k] = fmaf(s00, x0, fmaf(s10, x1, pa0[k]));
        pa1[k] = fmaf(s01, x0, fmaf(s11, x1, pa1[k]));
    }
    // -------- load gallery raw (fused B partials) --------
    float gb0[16], gb1[16];
    #pragma unroll
    for (int k = 0; k < 16; k++) { gb0[k] = 0.f; gb1[k] = 0.f; }
    #pragma unroll
    for (int k = 0; k < 16; k++) {
        const int g = warp + 4 * k;               // 64 gallery rows
        const float* src = gal + (size_t)(bg + g) * F + fbase;
        const float x0 = src[lane];
        const float x1 = src[lane + 32];
        sG[lane][g]      = x0;
        sG[lane + 32][g] = x1;
        gb0[k] = fmaf(w0r[0] * x0, x0, fmaf(w0r[1] * x1, x1, gb0[k]));
        gb1[k] = fmaf(w1r[0] * x0, x0, fmaf(w1r[1] * x1, x1, gb1[k]));
    }
    __syncthreads();

    // -------- mainloop: 3 LDS.128 + 8 FFMA2 per f, zero MOVs --------
    const int ty = tid >> 4;      // 0..7  -> probe pair
    const int tx = tid & 15;      // 0..15 -> gallery quad
    const int tp = 2 * ty;
    const int tg = 4 * tx;

    unsigned long long A0a = 0, A0b = 0, A1a = 0, A1b = 0;  // probe tp
    unsigned long long B0a = 0, B0b = 0, B1a = 0, B1b = 0;  // probe tp+1

    ulonglong2 Pa = *(const ulonglong2*)&sPd[0][2 * tp];      // probe tp : (c0,c1) dup'd
    ulonglong2 Pb = *(const ulonglong2*)&sPd[0][2 * tp + 2];  // probe tp+1
    ulonglong2 G  = *(const ulonglong2*)&sG[0][tg];           // (g0,g1),(g2,g3)
    #pragma unroll
    for (int f = 0; f < KC; f++) {
        const ulonglong2 Pan = *(const ulonglong2*)&sPd[f + 1][2 * tp];      // row KC = pad
        const ulonglong2 Pbn = *(const ulonglong2*)&sPd[f + 1][2 * tp + 2];
        const ulonglong2 Gn  = *(const ulonglong2*)&sG[f + 1][tg];
        A0a = fma2(Pa.x, G.x, A0a);
        A0b = fma2(Pa.x, G.y, A0b);
        A1a = fma2(Pa.y, G.x, A1a);
        A1b = fma2(Pa.y, G.y, A1b);
        B0a = fma2(Pb.x, G.x, B0a);
        B0b = fma2(Pb.x, G.y, B0b);
        B1a = fma2(Pb.y, G.x, B1a);
        B1b = fma2(Pb.y, G.y, B1b);
        Pa = Pan; Pb = Pbn; G = Gn;
    }
    __syncthreads();

    // -------- reduce A/B partials across lanes into smem --------
    #pragma unroll
    for (int k = 0; k < 4; k++) {
        float r0 = pa0[k], r1 = pa1[k];
        #pragma unroll
        for (int o = 16; o > 0; o >>= 1) {
            r0 += __shfl_down_sync(0xffffffffu, r0, o);
            r1 += __shfl_down_sync(0xffffffffu, r1, o);
        }
        if (lane == 0) sA[warp + 4 * k] = make_float2(r0, r1);
    }
    #pragma unroll
    for (int k = 0; k < 16; k++) {
        float r0 = gb0[k], r1 = gb1[k];
        #pragma unroll
        for (int o = 16; o > 0; o >>= 1) {
            r0 += __shfl_down_sync(0xffffffffu, r0, o);
            r1 += __shfl_down_sync(0xffffffffu, r1, o);
        }
        if (lane == 0) sB[warp + 4 * k] = make_float2(r0, r1);
    }
    __syncthreads();

    // -------- epilogue: atomicAdd partial (A+B+K-2*cross) into zeroed out --------
    float2 Bv[4];
    #pragma unroll
    for (int j = 0; j < 4; j++) Bv[j] = sB[tg + j];

    #pragma unroll
    for (int i = 0; i < 2; i++) {
        const float2 Ap = sA[tp + i];
        const float ax = Ap.x + kc0;
        const float ay = Ap.y + kc1;
        const float2 c0a = unpack2(i == 0 ? A0a : B0a);   // c0 @ (g0,g1)
        const float2 c0b = unpack2(i == 0 ? A0b : B0b);   // c0 @ (g2,g3)
        const float2 c1a = unpack2(i == 0 ? A1a : B1a);   // c1 @ (g0,g1)
        const float2 c1b = unpack2(i == 0 ? A1b : B1b);   // c1 @ (g2,g3)
        float* dst = out + ((size_t)(bp + tp + i) * NG + bg + tg) * 2;
        atomicAdd(dst + 0, fmaf(-2.0f, c0a.x, ax + Bv[0].x));
        atomicAdd(dst + 1, fmaf(-2.0f, c1a.x, ay + Bv[0].y));
        atomicAdd(dst + 2, fmaf(-2.0f, c0a.y, ax + Bv[1].x));
        atomicAdd(dst + 3, fmaf(-2.0f, c1a.y, ay + Bv[1].y));
        atomicAdd(dst + 4, fmaf(-2.0f, c0b.x, ax + Bv[2].x));
        atomicAdd(dst + 5, fmaf(-2.0f, c1b.x, ay + Bv[2].y));
        atomicAdd(dst + 6, fmaf(-2.0f, c0b.y, ax + Bv[3].x));
        atomicAdd(dst + 7, fmaf(-2.0f, c1b.y, ay + Bv[3].y));
    }
}

// ---------------- launch: memset + ONE kernel (both graph-capturable) ----------------
extern "C" void kernel_launch(void* const* d_in, const int* in_sizes, int n_in,
                              void* d_out, int out_size) {
    const float* probe = (const float*)d_in[0];
    const float* gal   = (const float*)d_in[1];
    const float* bnw   = (const float*)d_in[2];
    const float* bnb   = (const float*)d_in[3];
    const float* bnm   = (const float*)d_in[4];
    const float* bnv   = (const float*)d_in[5];
    const float* W     = (const float*)d_in[6];
    const float* bias  = (const float*)d_in[7];
    float* out = (float*)d_out;

    cudaMemsetAsync(out, 0, (size_t)out_size * sizeof(float));
    dim3 grid(NG / TG, NP / TP, F / KC);   // (16, 16, 2) = 512 blocks, one wave
    cls_kernel<<<grid, THREADS>>>(probe, gal, bnw, bnb, bnm, bnv, W, bias, out);
}

// round 11
// speedup vs baseline: 1.3419x; 1.3419x over previous
#include <cuda_runtime.h>
#include <mma.h>
#include <cstdint>

using namespace nvcuda;

#define NP 256
#define NG 1024
#define F  128
#define EPSV 1e-5f

#define BN 64      // gallery per block
#define BP 32      // probes per block (M = 64 rows = 32p x 2c interleaved)
#define KC 64      // K-chunk
#define THREADS 128
#define LDA 72
#define LDB 72
#define LDC 68

typedef wmma::fragment<wmma::matrix_a, 16, 16, 8, wmma::precision::tf32, wmma::row_major> FragA;
typedef wmma::fragment<wmma::matrix_b, 16, 16, 8, wmma::precision::tf32, wmma::col_major> FragB;
typedef wmma::fragment<wmma::accumulator, 16, 16, 8, float> FragC;

template <typename Frag>
__device__ __forceinline__ void split_tf32(Frag& hi, Frag& lo) {
    for (int e = 0; e < hi.num_elements; e++) {
        const float v = hi.x[e];
        const float hv = wmma::__float_to_tf32(v);
        hi.x[e] = hv;
        lo.x[e] = wmma::__float_to_tf32(v - hv);
    }
}

// out[p,g,c] = A2[p,c] + B2[g,c] + K[c] - 2 * sum_f (p_f w'_cf) g_f
// Cross term on tensor cores: tf32 wmma, 3xTF32 hi/lo compensation (fp32-accurate).
__global__ void __launch_bounds__(THREADS) cls_kernel(
    const float* __restrict__ probe, const float* __restrict__ gal,
    const float* __restrict__ bnw, const float* __restrict__ bnb,
    const float* __restrict__ bnm, const float* __restrict__ bnv,
    const float* __restrict__ W, const float* __restrict__ bias,
    float* __restrict__ out)
{
    __shared__ __align__(16) float As[2 * BP * LDA];  // [m=2p+c][f_loc]; reused for cross
    __shared__ __align__(16) float Gs[BN * LDB];      // [g][f_loc]
    __shared__ __align__(16) float sW0[F];
    __shared__ __align__(16) float sW1[F];
    __shared__ float2 sA2[BP];
    __shared__ float2 sB2[BN];
    __shared__ float2 sK4[4];

    const int tid  = threadIdx.x;
    const int lane = tid & 31;
    const int warp = tid >> 5;       // 0..3
    const int bp = blockIdx.y * BP;
    const int bg = blockIdx.x * BN;

    // -------- folded weights + K reduction (thread == feature) --------
    {
        const int f = tid;
        const float inv = bnw[f] * rsqrtf(bnv[f] + EPSV);
        const float Wf0 = W[f], Wf1 = W[F + f];
        sW0[f] = Wf0 * inv;
        sW1[f] = Wf1 * inv;
        const float off = bnb[f] - bnm[f] * inv;
        float k0 = Wf0 * off, k1 = Wf1 * off;
        for (int o = 16; o > 0; o >>= 1) {
            k0 += __shfl_down_sync(0xffffffffu, k0, o);
            k1 += __shfl_down_sync(0xffffffffu, k1, o);
        }
        if (lane == 0)
            sK4[warp] = make_float2(k0 + (warp == 0 ? bias[0] : 0.f),
                                    k1 + (warp == 0 ? bias[1] : 0.f));
    }
    __syncthreads();

    float pa0 = 0.f, pa1 = 0.f;      // A2 partial, probe r = tid>>2
    float gb0 = 0.f, gb1 = 0.f;      // B2 partial, gallery g = tid>>1

    FragC acc[4];
    for (int t = 0; t < 4; t++) wmma::fill_fragment(acc[t], 0.f);

    const int r = tid >> 2, q = tid & 3;
    const int g = tid >> 1, h = tid & 1;

    for (int kc = 0; kc < F; kc += KC) {
        __syncthreads();   // protect As/Gs from prior chunk's MMA reads

        // ---- A-tile: scaled probes, class-interleaved rows; fused A2 ----
        for (int j = 0; j < 4; j++) {
            const int col = 4 * q + 16 * j;
            const float4 x  = *(const float4*)(probe + (size_t)(bp + r) * F + kc + col);
            const float4 w0 = *(const float4*)&sW0[kc + col];
            const float4 w1 = *(const float4*)&sW1[kc + col];
            float4 a0, a1;
            a0.x = x.x * w0.x; a0.y = x.y * w0.y; a0.z = x.z * w0.z; a0.w = x.w * w0.w;
            a1.x = x.x * w1.x; a1.y = x.y * w1.y; a1.z = x.z * w1.z; a1.w = x.w * w1.w;
            *(float4*)&As[(2 * r)     * LDA + col] = a0;
            *(float4*)&As[(2 * r + 1) * LDA + col] = a1;
            pa0 += a0.x * x.x + a0.y * x.y + a0.z * x.z + a0.w * x.w;
            pa1 += a1.x * x.x + a1.y * x.y + a1.z * x.z + a1.w * x.w;
        }
        // ---- G-tile: raw gallery; fused B2 ----
        for (int j = 0; j < 8; j++) {
            const int col = 32 * h + 4 * j;
            const float4 x  = *(const float4*)(gal + (size_t)(bg + g) * F + kc + col);
            const float4 w0 = *(const float4*)&sW0[kc + col];
            const float4 w1 = *(const float4*)&sW1[kc + col];
            *(float4*)&Gs[g * LDB + col] = x;
            const float xx = x.x * x.x, yy = x.y * x.y, zz = x.z * x.z, ww = x.w * x.w;
            gb0 += w0.x * xx + w0.y * yy + w0.z * zz + w0.w * ww;
            gb1 += w1.x * xx + w1.y * yy + w1.z * zz + w1.w * ww;
        }
        __syncthreads();

        // ---- tensor mainloop: 3xTF32 ----
        for (int s = 0; s < 8; s++) {
            FragA a_hi, a_lo;
            wmma::load_matrix_sync(a_hi, &As[(16 * warp) * LDA + 8 * s], LDA);
            split_tf32(a_hi, a_lo);
            for (int t = 0; t < 4; t++) {
                FragB b_hi, b_lo;
                wmma::load_matrix_sync(b_hi, &Gs[(16 * t) * LDB + 8 * s], LDB);
                split_tf32(b_hi, b_lo);
                wmma::mma_sync(acc[t], a_hi, b_hi, acc[t]);
                wmma::mma_sync(acc[t], a_hi, b_lo, acc[t]);
                wmma::mma_sync(acc[t], a_lo, b_hi, acc[t]);
            }
        }
    }

    // -------- reduce diag partials --------
    pa0 += __shfl_down_sync(0xffffffffu, pa0, 2, 4);
    pa0 += __shfl_down_sync(0xffffffffu, pa0, 1, 4);
    pa1 += __shfl_down_sync(0xffffffffu, pa1, 2, 4);
    pa1 += __shfl_down_sync(0xffffffffu, pa1, 1, 4);
    if (q == 0) sA2[r] = make_float2(pa0, pa1);
    gb0 += __shfl_down_sync(0xffffffffu, gb0, 1, 2);
    gb1 += __shfl_down_sync(0xffffffffu, gb1, 1, 2);
    if (h == 0) sB2[g] = make_float2(gb0, gb1);

    __syncthreads();   // all MMA reads of As/Gs done before scratch reuse

    // -------- spill cross tiles to smem (reuse As, stride LDC) --------
    for (int t = 0; t < 4; t++)
        wmma::store_matrix_sync(&As[(16 * warp) * LDC + 16 * t], acc[t], LDC,
                                wmma::mem_row_major);
    __syncthreads();

    // -------- epilogue --------
    const float2 K01 = make_float2(sK4[0].x + sK4[1].x + sK4[2].x + sK4[3].x,
                                   sK4[0].y + sK4[1].y + sK4[2].y + sK4[3].y);
    for (int it = 0; it < 16; it++) {
        const int idx = tid + THREADS * it;      // 0..2047
        const int i = idx >> 6;                  // probe 0..31
        const int gg = idx & 63;                 // gallery 0..63
        const float c0 = As[(2 * i)     * LDC + gg];
        const float c1 = As[(2 * i + 1) * LDC + gg];
        const float2 a2 = sA2[i];
        const float2 b2 = sB2[gg];
        float2 o;
        o.x = fmaf(-2.0f, c0, a2.x + b2.x + K01.x);
        o.y = fmaf(-2.0f, c1, a2.y + b2.y + K01.y);
        *(float2*)(out + ((size_t)(bp + i) * NG + bg + gg) * 2) = o;
    }
}

// ---------------- launch: ONE kernel ----------------
extern "C" void kernel_launch(void* const* d_in, const int* in_sizes, int n_in,
                              void* d_out, int out_size) {
    const float* probe = (const float*)d_in[0];
    const float* gal   = (const float*)d_in[1];
    const float* bnw   = (const float*)d_in[2];
    const float* bnb   = (const float*)d_in[3];
    const float* bnm   = (const float*)d_in[4];
    const float* bnv   = (const float*)d_in[5];
    const float* W     = (const float*)d_in[6];
    const float* bias  = (const float*)d_in[7];
    float* out = (float*)d_out;

    dim3 grid(NG / BN, NP / BP);   // (16, 8) = 128 blocks x 128 threads
    cls_kernel<<<grid, THREADS>>>(probe, gal, bnw, bnb, bnm, bnv, W, bias, out);
}